// round 14
// baseline (speedup 1.0000x reference)
#include <cuda_runtime.h>
#include <cuda_fp16.h>
#include <cstdint>

#define HD 64
#define FULL 0xFFFFFFFFu

static const int N_CAP = 100000;
static const int E_CAP = 1200000;
static const int G_CAP = 256;

// Scratch (allocation-free: __device__ globals; only referenced in device code)
__device__ int    g_deg[N_CAP];
__device__ int    g_off[N_CAP];
__device__ int    g_cur[N_CAP];
__device__ int    g_total;
__device__ int2   g_csr[E_CAP];          // {src, w bits}
__device__ float  g_agg1[N_CAP];         // layer-1 scalar aggregation (filled by fill_kernel)
__device__ __half g_h1[N_CAP * HD];      // fp16 node features (layer1 out)
__device__ __half g_h2[N_CAP * HD];      // fp16 node features (layer2 out)
__device__ __half g_agg[N_CAP * HD];     // fp16 aggregation result
__device__ __align__(16) __half g_w16[2 * 64 * 128];  // pre-swizzled [Wrel;Wroot]^T fp16
__device__ float  g_sums[G_CAP * HD];
__device__ float  g_cnt[G_CAP];

__device__ __forceinline__ void red_add_v2(float* p, float x, float y) {
    asm volatile("red.global.add.v2.f32 [%0], {%1,%2};"
                 :: "l"(p), "f"(x), "f"(y) : "memory");
}
__device__ __forceinline__ void red_add_f(float* p, float x) {
    asm volatile("red.global.add.f32 [%0], %1;" :: "l"(p), "f"(x) : "memory");
}

// mma.sync m16n8k16 fp16 -> fp32
__device__ __forceinline__ void mma16816(float* c,
        uint32_t a0, uint32_t a1, uint32_t a2, uint32_t a3,
        uint32_t b0, uint32_t b1) {
    asm volatile(
        "mma.sync.aligned.m16n8k16.row.col.f32.f16.f16.f32 "
        "{%0,%1,%2,%3}, {%4,%5,%6,%7}, {%8,%9}, {%0,%1,%2,%3};"
        : "+f"(c[0]), "+f"(c[1]), "+f"(c[2]), "+f"(c[3])
        : "r"(a0), "r"(a1), "r"(a2), "r"(a3), "r"(b0), "r"(b1));
}

// swizzled half2 load from a [row][128] fp16 tile: 16B chunk c stored at c^(row&7)
__device__ __forceinline__ uint32_t ld_sw(const __half* base, int row, int k) {
    int chunk = (k >> 3) ^ (row & 7);
    return *(const uint32_t*)(base + row * 128 + chunk * 8 + (k & 7));
}

// ---------------- init + weight preconversion ----------------
__global__ void init_kernel(const float* __restrict__ W2rel, const float* __restrict__ W2root,
                            const float* __restrict__ W3rel, const float* __restrict__ W3root,
                            int n, int g) {
    int i = blockIdx.x * blockDim.x + threadIdx.x;
    int stride = gridDim.x * blockDim.x;
    for (int k = i; k < n; k += stride) { g_deg[k] = 0; g_agg1[k] = 0.f; }
    int sv = g * HD;
    for (int k = i; k < sv; k += stride) g_sums[k] = 0.f;
    for (int k = i; k < g; k += stride) g_cnt[k] = 0.f;
    if (i == 0) g_total = 0;
    for (int idx = i; idx < 16384; idx += stride) {
        int L = idx >> 13;
        int r = idx & 8191;
        int k = r >> 6, j = r & 63;
        const float* Wrel  = L ? W3rel : W2rel;
        const float* Wroot = L ? W3root : W2root;
        float wv = (k < 64) ? __ldg(Wrel + k * 64 + j) : __ldg(Wroot + (k - 64) * 64 + j);
        int chunk = (k >> 3) ^ (j & 7);
        g_w16[L * 8192 + j * 128 + chunk * 8 + (k & 7)] = __float2half_rn(wv);
    }
}

// ---------------- CSR build ----------------
__global__ void hist_kernel(const int* __restrict__ dst, int E) {
    int t = blockIdx.x * blockDim.x + threadIdx.x;
    int i = t * 4;
    if (i + 3 < E) {
        int4 d = __ldg((const int4*)(dst + i));
        atomicAdd(&g_deg[d.x], 1);
        atomicAdd(&g_deg[d.y], 1);
        atomicAdd(&g_deg[d.z], 1);
        atomicAdd(&g_deg[d.w], 1);
    } else {
        for (int e = i; e < E; e++) atomicAdd(&g_deg[dst[e]], 1);
    }
}

// warp-aggregated: inclusive scan, one atomicAdd per warp
__global__ void offs_kernel(int n) {
    int i = blockIdx.x * blockDim.x + threadIdx.x;
    int lane = threadIdx.x & 31;
    int d = (i < n) ? g_deg[i] : 0;
    int s = d;
#pragma unroll
    for (int o = 1; o < 32; o <<= 1) {
        int t = __shfl_up_sync(FULL, s, o);
        if (lane >= o) s += t;
    }
    int wsum = __shfl_sync(FULL, s, 31);
    int base = 0;
    if (lane == 31) base = atomicAdd(&g_total, wsum);
    base = __shfl_sync(FULL, base, 31);
    if (i < n) {
        int o = base + s - d;    // exclusive
        g_off[i] = o;
        g_cur[i] = o;
    }
}

// fill CSR + layer-1 scalar aggregation (agg1[dst] += w * x[src])
__global__ void fill_kernel(const int* __restrict__ src, const int* __restrict__ dst,
                            const float* __restrict__ ew, const float* __restrict__ x, int E) {
    int e0 = (blockIdx.x * blockDim.x + threadIdx.x) * 2;
    if (e0 >= E) return;
    int d0 = __ldg(dst + e0), s0 = __ldg(src + e0);
    float w0 = __ldg(ew + e0);
    int e1 = e0 + 1;
    int d1 = 0, s1 = 0; float w1 = 0.f;
    bool has1 = e1 < E;
    if (has1) { d1 = __ldg(dst + e1); s1 = __ldg(src + e1); w1 = __ldg(ew + e1); }
    float x0 = __ldg(x + s0);
    float x1 = has1 ? __ldg(x + s1) : 0.f;
    int p0 = atomicAdd(&g_cur[d0], 1);
    g_csr[p0] = make_int2(s0, __float_as_int(w0));
    red_add_f(&g_agg1[d0], w0 * x0);
    if (has1) {
        int p1 = atomicAdd(&g_cur[d1], 1);
        g_csr[p1] = make_int2(s1, __float_as_int(w1));
        red_add_f(&g_agg1[d1], w1 * x1);
    }
}

// ---------------- layer 1 node transform (agg1 precomputed by fill) ----------------
__global__ void node1_kernel(const float* __restrict__ x, const int* __restrict__ batch,
                             const float* __restrict__ Wrel, const float* __restrict__ b,
                             const float* __restrict__ Wroot, int n) {
    int idx = blockIdx.x * blockDim.x + threadIdx.x;
    if (idx >= n * 8) return;
    int node = idx >> 3, c8 = idx & 7;
    float a = g_agg1[node];
    float xv = __ldg(x + node);
    float4 wr0 = __ldg((const float4*)Wrel + c8 * 2);
    float4 wr1 = __ldg((const float4*)Wrel + c8 * 2 + 1);
    float4 wo0 = __ldg((const float4*)Wroot + c8 * 2);
    float4 wo1 = __ldg((const float4*)Wroot + c8 * 2 + 1);
    float4 bb0 = __ldg((const float4*)b + c8 * 2);
    float4 bb1 = __ldg((const float4*)b + c8 * 2 + 1);
    float h0 = fmaxf(fmaf(a, wr0.x, fmaf(xv, wo0.x, bb0.x)), 0.f);
    float h1 = fmaxf(fmaf(a, wr0.y, fmaf(xv, wo0.y, bb0.y)), 0.f);
    float h2 = fmaxf(fmaf(a, wr0.z, fmaf(xv, wo0.z, bb0.z)), 0.f);
    float h3 = fmaxf(fmaf(a, wr0.w, fmaf(xv, wo0.w, bb0.w)), 0.f);
    float h4 = fmaxf(fmaf(a, wr1.x, fmaf(xv, wo1.x, bb1.x)), 0.f);
    float h5 = fmaxf(fmaf(a, wr1.y, fmaf(xv, wo1.y, bb1.y)), 0.f);
    float h6 = fmaxf(fmaf(a, wr1.z, fmaf(xv, wo1.z, bb1.z)), 0.f);
    float h7 = fmaxf(fmaf(a, wr1.w, fmaf(xv, wo1.w, bb1.w)), 0.f);
    __half2 p0 = __floats2half2_rn(h0, h1);
    __half2 p1 = __floats2half2_rn(h2, h3);
    __half2 p2 = __floats2half2_rn(h4, h5);
    __half2 p3 = __floats2half2_rn(h6, h7);
    *(int4*)(g_h1 + node * HD + c8 * 8) =
        make_int4(*(int*)&p0, *(int*)&p1, *(int*)&p2, *(int*)&p3);
    if (c8 == 0) atomicAdd(&g_cnt[batch[node]], 1.0f);
}

// ---------------- layer-2 aggregation via h1 reconstruction (rank-2 trick) ----------
// h1[s][c] = relu(agg1[s]*wr[c] + x[s]*wo[c] + b[c]) — gather only 2 scalars per edge.
__global__ void aggH2_kernel(const float* __restrict__ x, const float* __restrict__ W1rel,
                             const float* __restrict__ b1, const float* __restrict__ W1root,
                             int n) {
    int gtid = blockIdx.x * blockDim.x + threadIdx.x;
    int node = gtid >> 5, lane = gtid & 31;
    if (node >= n) return;

    int c = lane * 2;
    float wr0 = __ldg(W1rel + c), wr1 = __ldg(W1rel + c + 1);
    float wo0 = __ldg(W1root + c), wo1 = __ldg(W1root + c + 1);
    float bb0 = __ldg(b1 + c), bb1 = __ldg(b1 + c + 1);

    int off = g_off[node], end = off + g_deg[node];
    float a0 = 0.f, a1 = 0.f;

    int i = off;
#pragma unroll 1
    for (; i + 4 <= end; i += 4) {
        int2 p[4]; float ag[4], xs[4];
#pragma unroll
        for (int j = 0; j < 4; j++) p[j] = __ldg(g_csr + i + j);
#pragma unroll
        for (int j = 0; j < 4; j++) { ag[j] = __ldg(g_agg1 + p[j].x); xs[j] = __ldg(x + p[j].x); }
#pragma unroll
        for (int j = 0; j < 4; j++) {
            float w = __int_as_float(p[j].y);
            float h0 = fmaxf(fmaf(ag[j], wr0, fmaf(xs[j], wo0, bb0)), 0.f);
            float h1 = fmaxf(fmaf(ag[j], wr1, fmaf(xs[j], wo1, bb1)), 0.f);
            a0 = fmaf(w, h0, a0); a1 = fmaf(w, h1, a1);
        }
    }
    for (; i < end; i++) {
        int2 p = __ldg(g_csr + i);
        float ag = __ldg(g_agg1 + p.x), xs = __ldg(x + p.x);
        float w = __int_as_float(p.y);
        float h0 = fmaxf(fmaf(ag, wr0, fmaf(xs, wo0, bb0)), 0.f);
        float h1 = fmaxf(fmaf(ag, wr1, fmaf(xs, wo1, bb1)), 0.f);
        a0 = fmaf(w, h0, a0); a1 = fmaf(w, h1, a1);
    }
    ((__half2*)(g_agg + node * HD))[lane] = __floats2half2_rn(a0, a1);
}

// ---------------- layer-3 aggregation: gather h2 rows (full rank) ----------------
__global__ void aggH3_kernel(int n) {
    const __half* __restrict__ hin = g_h2;
    int gtid = blockIdx.x * blockDim.x + threadIdx.x;
    int node = gtid >> 5, lane = gtid & 31;
    if (node >= n) return;

    int off = g_off[node], end = off + g_deg[node];
    float a0 = 0.f, a1 = 0.f;

    int i = off;
#pragma unroll 1
    for (; i + 8 <= end; i += 8) {
        int2 p[8];
#pragma unroll
        for (int j = 0; j < 8; j++) p[j] = __ldg(g_csr + i + j);
        __half2 v[8];
#pragma unroll
        for (int j = 0; j < 8; j++)
            v[j] = __ldg((const __half2*)(hin + p[j].x * HD) + lane);
#pragma unroll
        for (int j = 0; j < 8; j++) {
            float2 f = __half22float2(v[j]);
            float w = __int_as_float(p[j].y);
            a0 = fmaf(w, f.x, a0); a1 = fmaf(w, f.y, a1);
        }
    }
#pragma unroll 1
    for (; i + 4 <= end; i += 4) {
        int2 p[4];
#pragma unroll
        for (int j = 0; j < 4; j++) p[j] = __ldg(g_csr + i + j);
        __half2 v[4];
#pragma unroll
        for (int j = 0; j < 4; j++)
            v[j] = __ldg((const __half2*)(hin + p[j].x * HD) + lane);
#pragma unroll
        for (int j = 0; j < 4; j++) {
            float2 f = __half22float2(v[j]);
            float w = __int_as_float(p[j].y);
            a0 = fmaf(w, f.x, a0); a1 = fmaf(w, f.y, a1);
        }
    }
    for (; i < end; i++) {
        int2 p = __ldg(g_csr + i);
        __half2 v = __ldg((const __half2*)(hin + p.x * HD) + lane);
        float2 f = __half22float2(v);
        float w = __int_as_float(p.y);
        a0 = fmaf(w, f.x, a0); a1 = fmaf(w, f.y, a1);
    }
    ((__half2*)(g_agg + node * HD))[lane] = __floats2half2_rn(a0, a1);
}

// ---------------- tensor-core node GEMM: out = [agg|h] @ [Wrel;Wroot] + b -----------
template <int LAYER>
__global__ void __launch_bounds__(256) gemm_mma_kernel(
        const float* __restrict__ bias, const int* __restrict__ batch, int n) {
    __shared__ __align__(16) __half sA[128 * 128];   // [node][k], swizzled
    __shared__ __align__(16) __half sWt[64 * 128];   // [j][k],    swizzled
    const __half* Hin = (LAYER == 2) ? g_h1 : g_h2;
    const __half* Wt = g_w16 + ((LAYER == 2) ? 0 : 8192);
    int tid = threadIdx.x;
    int n0 = blockIdx.x * 128;

#pragma unroll
    for (int i = 0; i < 4; i++)
        ((int4*)sWt)[tid + i * 256] = __ldg((const int4*)Wt + tid + i * 256);

    for (int i = tid; i < 2048; i += 256) {
        int node = i >> 4, c4 = i & 15;
        int gn = n0 + node;
        int2 ra = make_int2(0, 0), rh = make_int2(0, 0);
        if (gn < n) {
            ra = __ldg((const int2*)(g_agg + gn * HD) + c4);
            rh = __ldg((const int2*)(Hin + gn * HD) + c4);
        }
        int k = c4 * 4;
        int chunk = (k >> 3) ^ (node & 7);
        __half* p = sA + node * 128 + chunk * 8 + (k & 7);
        *(int*)p       = ra.x;
        *(int*)(p + 2) = ra.y;
        k = 64 + c4 * 4;
        chunk = (k >> 3) ^ (node & 7);
        p = sA + node * 128 + chunk * 8 + (k & 7);
        *(int*)p       = rh.x;
        *(int*)(p + 2) = rh.y;
    }
    __syncthreads();

    int lane = tid & 31, warp = tid >> 5;
    int wm = warp & 3, wn = warp >> 2;
    int m0 = wm * 32;
    int gid = lane >> 2, tid4 = lane & 3;

    float acc[2][4][4];
#pragma unroll
    for (int mt = 0; mt < 2; mt++)
#pragma unroll
        for (int nt = 0; nt < 4; nt++)
#pragma unroll
            for (int q = 0; q < 4; q++) acc[mt][nt][q] = 0.f;

#pragma unroll
    for (int ks = 0; ks < 8; ks++) {
        int k0 = ks * 16 + tid4 * 2;
        int k1 = k0 + 8;
        uint32_t a[2][4];
#pragma unroll
        for (int mt = 0; mt < 2; mt++) {
            int row0 = m0 + mt * 16 + gid;
            int row1 = row0 + 8;
            a[mt][0] = ld_sw(sA, row0, k0);
            a[mt][1] = ld_sw(sA, row1, k0);
            a[mt][2] = ld_sw(sA, row0, k1);
            a[mt][3] = ld_sw(sA, row1, k1);
        }
#pragma unroll
        for (int nt = 0; nt < 4; nt++) {
            int j = wn * 32 + nt * 8 + gid;
            uint32_t b0 = ld_sw(sWt, j, k0);
            uint32_t b1 = ld_sw(sWt, j, k1);
            mma16816(acc[0][nt], a[0][0], a[0][1], a[0][2], a[0][3], b0, b1);
            mma16816(acc[1][nt], a[1][0], a[1][1], a[1][2], a[1][3], b0, b1);
        }
    }

    int crow = gid;
    int ccol = tid4 * 2;
#pragma unroll
    for (int nt = 0; nt < 4; nt++) {
        int j = wn * 32 + nt * 8 + ccol;
        float2 bb = __ldg((const float2*)(bias + j));
#pragma unroll
        for (int mt = 0; mt < 2; mt++) {
            int nodeA = n0 + m0 + mt * 16 + crow;
            int nodeB = nodeA + 8;
            float o0 = acc[mt][nt][0] + bb.x;
            float o1 = acc[mt][nt][1] + bb.y;
            float o2 = acc[mt][nt][2] + bb.x;
            float o3 = acc[mt][nt][3] + bb.y;
            if (LAYER == 2) {
                o0 = fmaxf(o0, 0.f); o1 = fmaxf(o1, 0.f);
                o2 = fmaxf(o2, 0.f); o3 = fmaxf(o3, 0.f);
                if (nodeA < n) *(__half2*)(g_h2 + nodeA * HD + j) = __floats2half2_rn(o0, o1);
                if (nodeB < n) *(__half2*)(g_h2 + nodeB * HD + j) = __floats2half2_rn(o2, o3);
            } else {
                if (nodeA < n) red_add_v2(g_sums + __ldg(batch + nodeA) * HD + j, o0, o1);
                if (nodeB < n) red_add_v2(g_sums + __ldg(batch + nodeB) * HD + j, o2, o3);
            }
        }
    }
}

// ---------------- head ----------------
__global__ void head_kernel(const float* __restrict__ Wlin, const float* __restrict__ blin,
                            float* __restrict__ out, int g) {
    int idx = blockIdx.x * blockDim.x + threadIdx.x;
    if (idx >= g * 2) return;
    int gi = idx >> 1, c = idx & 1;
    float inv = 1.0f / fmaxf(g_cnt[gi], 1.0f);
    float acc = 0.f;
#pragma unroll
    for (int k = 0; k < HD; k++)
        acc = fmaf(g_sums[gi * HD + k], Wlin[k * 2 + c], acc);
    out[idx] = fmaf(acc, inv, blin[c]);
}

extern "C" void kernel_launch(void* const* d_in, const int* in_sizes, int n_in,
                              void* d_out, int out_size) {
    const float* x      = (const float*)d_in[0];
    const int*   ei     = (const int*)d_in[1];
    const int*   batch  = (const int*)d_in[2];
    const float* ew     = (const float*)d_in[3];
    const float* W1rel  = (const float*)d_in[4];
    const float* b1     = (const float*)d_in[5];
    const float* W1root = (const float*)d_in[6];
    const float* W2rel  = (const float*)d_in[7];
    const float* b2     = (const float*)d_in[8];
    const float* W2root = (const float*)d_in[9];
    const float* W3rel  = (const float*)d_in[10];
    const float* b3     = (const float*)d_in[11];
    const float* W3root = (const float*)d_in[12];
    const float* Wlin   = (const float*)d_in[13];
    const float* blin   = (const float*)d_in[14];

    int N = in_sizes[0];        // x is [N,1]
    int E = in_sizes[3];        // edge_weight is [E]
    int G = out_size / 2;

    const int* src = ei;
    const int* dst = ei + E;
    float* out = (float*)d_out;

    init_kernel<<<256, 256>>>(W2rel, W2root, W3rel, W3root, N, G);
    hist_kernel<<<(E / 4 + 256) / 256, 256>>>(dst, E);
    offs_kernel<<<(N + 255) / 256, 256>>>(N);
    fill_kernel<<<(E / 2 + 256) / 256, 256>>>(src, dst, ew, x, E);

    node1_kernel<<<(N * 8 + 255) / 256, 256>>>(x, batch, W1rel, b1, W1root, N);
    aggH2_kernel<<<(N * 32 + 255) / 256, 256>>>(x, W1rel, b1, W1root, N);
    gemm_mma_kernel<2><<<(N + 127) / 128, 256>>>(b2, batch, N);
    aggH3_kernel<<<(N * 32 + 255) / 256, 256>>>(N);
    gemm_mma_kernel<3><<<(N + 127) / 128, 256>>>(b3, batch, N);
    head_kernel<<<(G * 2 + 255) / 256, 256>>>(Wlin, blin, out, G);
}

// round 15
// speedup vs baseline: 1.0504x; 1.0504x over previous
#include <cuda_runtime.h>
#include <cuda_fp16.h>
#include <cstdint>

#define HD 64
#define FULL 0xFFFFFFFFu

static const int N_CAP = 100000;
static const int E_CAP = 1200000;
static const int G_CAP = 256;

// Scratch (allocation-free: __device__ globals; only referenced in device code)
__device__ int    g_deg[N_CAP];
__device__ int    g_off[N_CAP];
__device__ int    g_cur[N_CAP];
__device__ int    g_total;
__device__ __align__(16) int2 g_csr[E_CAP];   // {src, w bits}, 16B-aligned for int4 pair loads
__device__ float  g_agg1[N_CAP];
__device__ __half g_h1[N_CAP * HD];
__device__ __half g_h2[N_CAP * HD];
__device__ __half g_agg[N_CAP * HD];
__device__ __align__(16) __half g_w16[2 * 64 * 128];  // pre-swizzled [Wrel;Wroot]^T fp16
__device__ float  g_sums[G_CAP * HD];
__device__ float  g_cnt[G_CAP];

__device__ __forceinline__ void red_add_v2(float* p, float x, float y) {
    asm volatile("red.global.add.v2.f32 [%0], {%1,%2};"
                 :: "l"(p), "f"(x), "f"(y) : "memory");
}
__device__ __forceinline__ void red_add_f(float* p, float x) {
    asm volatile("red.global.add.f32 [%0], %1;" :: "l"(p), "f"(x) : "memory");
}

// mma.sync m16n8k16 fp16 -> fp32
__device__ __forceinline__ void mma16816(float* c,
        uint32_t a0, uint32_t a1, uint32_t a2, uint32_t a3,
        uint32_t b0, uint32_t b1) {
    asm volatile(
        "mma.sync.aligned.m16n8k16.row.col.f32.f16.f16.f32 "
        "{%0,%1,%2,%3}, {%4,%5,%6,%7}, {%8,%9}, {%0,%1,%2,%3};"
        : "+f"(c[0]), "+f"(c[1]), "+f"(c[2]), "+f"(c[3])
        : "r"(a0), "r"(a1), "r"(a2), "r"(a3), "r"(b0), "r"(b1));
}

// swizzled half2 load from a [row][128] fp16 tile: 16B chunk c stored at c^(row&7)
__device__ __forceinline__ uint32_t ld_sw(const __half* base, int row, int k) {
    int chunk = (k >> 3) ^ (row & 7);
    return *(const uint32_t*)(base + row * 128 + chunk * 8 + (k & 7));
}

// ---------------- init + weight preconversion ----------------
__global__ void init_kernel(const float* __restrict__ W2rel, const float* __restrict__ W2root,
                            const float* __restrict__ W3rel, const float* __restrict__ W3root,
                            int n, int g) {
    int i = blockIdx.x * blockDim.x + threadIdx.x;
    int stride = gridDim.x * blockDim.x;
    for (int k = i; k < n; k += stride) { g_deg[k] = 0; g_agg1[k] = 0.f; }
    int sv = g * HD;
    for (int k = i; k < sv; k += stride) g_sums[k] = 0.f;
    for (int k = i; k < g; k += stride) g_cnt[k] = 0.f;
    if (i == 0) g_total = 0;
    for (int idx = i; idx < 16384; idx += stride) {
        int L = idx >> 13;
        int r = idx & 8191;
        int k = r >> 6, j = r & 63;
        const float* Wrel  = L ? W3rel : W2rel;
        const float* Wroot = L ? W3root : W2root;
        float wv = (k < 64) ? __ldg(Wrel + k * 64 + j) : __ldg(Wroot + (k - 64) * 64 + j);
        int chunk = (k >> 3) ^ (j & 7);
        g_w16[L * 8192 + j * 128 + chunk * 8 + (k & 7)] = __float2half_rn(wv);
    }
}

// ---------------- CSR build ----------------
__global__ void hist_kernel(const int* __restrict__ dst, int E) {
    int i = (blockIdx.x * blockDim.x + threadIdx.x) * 8;
    if (i + 7 < E) {
        int4 d0 = __ldg((const int4*)(dst + i));
        int4 d1 = __ldg((const int4*)(dst + i + 4));
        atomicAdd(&g_deg[d0.x], 1);
        atomicAdd(&g_deg[d0.y], 1);
        atomicAdd(&g_deg[d0.z], 1);
        atomicAdd(&g_deg[d0.w], 1);
        atomicAdd(&g_deg[d1.x], 1);
        atomicAdd(&g_deg[d1.y], 1);
        atomicAdd(&g_deg[d1.z], 1);
        atomicAdd(&g_deg[d1.w], 1);
    } else {
        for (int e = i; e < E; e++) atomicAdd(&g_deg[dst[e]], 1);
    }
}

// warp-aggregated: inclusive scan, one atomicAdd per warp
__global__ void offs_kernel(int n) {
    int i = blockIdx.x * blockDim.x + threadIdx.x;
    int lane = threadIdx.x & 31;
    int d = (i < n) ? g_deg[i] : 0;
    int s = d;
#pragma unroll
    for (int o = 1; o < 32; o <<= 1) {
        int t = __shfl_up_sync(FULL, s, o);
        if (lane >= o) s += t;
    }
    int wsum = __shfl_sync(FULL, s, 31);
    int base = 0;
    if (lane == 31) base = atomicAdd(&g_total, wsum);
    base = __shfl_sync(FULL, base, 31);
    if (i < n) {
        int o = base + s - d;    // exclusive
        g_off[i] = o;
        g_cur[i] = o;
    }
}

// fill CSR + layer-1 scalar aggregation (agg1[dst] += w * x[src])
__global__ void fill_kernel(const int* __restrict__ src, const int* __restrict__ dst,
                            const float* __restrict__ ew, const float* __restrict__ x, int E) {
    int e0 = (blockIdx.x * blockDim.x + threadIdx.x) * 2;
    if (e0 >= E) return;
    int d0 = __ldg(dst + e0), s0 = __ldg(src + e0);
    float w0 = __ldg(ew + e0);
    int e1 = e0 + 1;
    int d1 = 0, s1 = 0; float w1 = 0.f;
    bool has1 = e1 < E;
    if (has1) { d1 = __ldg(dst + e1); s1 = __ldg(src + e1); w1 = __ldg(ew + e1); }
    float x0 = __ldg(x + s0);
    float x1 = has1 ? __ldg(x + s1) : 0.f;
    int p0 = atomicAdd(&g_cur[d0], 1);
    g_csr[p0] = make_int2(s0, __float_as_int(w0));
    red_add_f(&g_agg1[d0], w0 * x0);
    if (has1) {
        int p1 = atomicAdd(&g_cur[d1], 1);
        g_csr[p1] = make_int2(s1, __float_as_int(w1));
        red_add_f(&g_agg1[d1], w1 * x1);
    }
}

// ---------------- layer 1 node transform (agg1 precomputed by fill) ----------------
__global__ void node1_kernel(const float* __restrict__ x, const int* __restrict__ batch,
                             const float* __restrict__ Wrel, const float* __restrict__ b,
                             const float* __restrict__ Wroot, int n) {
    int idx = blockIdx.x * blockDim.x + threadIdx.x;
    if (idx >= n * 8) return;
    int node = idx >> 3, c8 = idx & 7;
    float a = g_agg1[node];
    float xv = __ldg(x + node);
    float4 wr0 = __ldg((const float4*)Wrel + c8 * 2);
    float4 wr1 = __ldg((const float4*)Wrel + c8 * 2 + 1);
    float4 wo0 = __ldg((const float4*)Wroot + c8 * 2);
    float4 wo1 = __ldg((const float4*)Wroot + c8 * 2 + 1);
    float4 bb0 = __ldg((const float4*)b + c8 * 2);
    float4 bb1 = __ldg((const float4*)b + c8 * 2 + 1);
    float h0 = fmaxf(fmaf(a, wr0.x, fmaf(xv, wo0.x, bb0.x)), 0.f);
    float h1 = fmaxf(fmaf(a, wr0.y, fmaf(xv, wo0.y, bb0.y)), 0.f);
    float h2 = fmaxf(fmaf(a, wr0.z, fmaf(xv, wo0.z, bb0.z)), 0.f);
    float h3 = fmaxf(fmaf(a, wr0.w, fmaf(xv, wo0.w, bb0.w)), 0.f);
    float h4 = fmaxf(fmaf(a, wr1.x, fmaf(xv, wo1.x, bb1.x)), 0.f);
    float h5 = fmaxf(fmaf(a, wr1.y, fmaf(xv, wo1.y, bb1.y)), 0.f);
    float h6 = fmaxf(fmaf(a, wr1.z, fmaf(xv, wo1.z, bb1.z)), 0.f);
    float h7 = fmaxf(fmaf(a, wr1.w, fmaf(xv, wo1.w, bb1.w)), 0.f);
    __half2 p0 = __floats2half2_rn(h0, h1);
    __half2 p1 = __floats2half2_rn(h2, h3);
    __half2 p2 = __floats2half2_rn(h4, h5);
    __half2 p3 = __floats2half2_rn(h6, h7);
    *(int4*)(g_h1 + node * HD + c8 * 8) =
        make_int4(*(int*)&p0, *(int*)&p1, *(int*)&p2, *(int*)&p3);
    if (c8 == 0) atomicAdd(&g_cnt[batch[node]], 1.0f);
}

// ---------------- H-layer aggregation: warp-per-node, lane = channel pair ----------
// CSR read as int4 (2 edges per uniform load) to cut LSU-issue count.
template <int LAYER>
__global__ void aggH_kernel(int n) {
    const __half* __restrict__ hin = (LAYER == 2) ? g_h1 : g_h2;
    int gtid = blockIdx.x * blockDim.x + threadIdx.x;
    int node = gtid >> 5, lane = gtid & 31;
    if (node >= n) return;

    int off = g_off[node], end = off + g_deg[node];
    float a0 = 0.f, a1 = 0.f;

    int i = off;
    // peel one edge if off is odd (keeps int4 loads 16B-aligned)
    if ((i & 1) && i < end) {
        int2 p = __ldg(g_csr + i);
        __half2 v = __ldg((const __half2*)(hin + p.x * HD) + lane);
        float2 f = __half22float2(v);
        float w = __int_as_float(p.y);
        a0 = fmaf(w, f.x, a0); a1 = fmaf(w, f.y, a1);
        i++;
    }
#pragma unroll 1
    for (; i + 8 <= end; i += 8) {
        int4 q0 = __ldg((const int4*)(g_csr + i));
        int4 q1 = __ldg((const int4*)(g_csr + i + 2));
        int4 q2 = __ldg((const int4*)(g_csr + i + 4));
        int4 q3 = __ldg((const int4*)(g_csr + i + 6));
        __half2 v0 = __ldg((const __half2*)(hin + q0.x * HD) + lane);
        __half2 v1 = __ldg((const __half2*)(hin + q0.z * HD) + lane);
        __half2 v2 = __ldg((const __half2*)(hin + q1.x * HD) + lane);
        __half2 v3 = __ldg((const __half2*)(hin + q1.z * HD) + lane);
        __half2 v4 = __ldg((const __half2*)(hin + q2.x * HD) + lane);
        __half2 v5 = __ldg((const __half2*)(hin + q2.z * HD) + lane);
        __half2 v6 = __ldg((const __half2*)(hin + q3.x * HD) + lane);
        __half2 v7 = __ldg((const __half2*)(hin + q3.z * HD) + lane);
        float2 f;
        f = __half22float2(v0); a0 = fmaf(__int_as_float(q0.y), f.x, a0); a1 = fmaf(__int_as_float(q0.y), f.y, a1);
        f = __half22float2(v1); a0 = fmaf(__int_as_float(q0.w), f.x, a0); a1 = fmaf(__int_as_float(q0.w), f.y, a1);
        f = __half22float2(v2); a0 = fmaf(__int_as_float(q1.y), f.x, a0); a1 = fmaf(__int_as_float(q1.y), f.y, a1);
        f = __half22float2(v3); a0 = fmaf(__int_as_float(q1.w), f.x, a0); a1 = fmaf(__int_as_float(q1.w), f.y, a1);
        f = __half22float2(v4); a0 = fmaf(__int_as_float(q2.y), f.x, a0); a1 = fmaf(__int_as_float(q2.y), f.y, a1);
        f = __half22float2(v5); a0 = fmaf(__int_as_float(q2.w), f.x, a0); a1 = fmaf(__int_as_float(q2.w), f.y, a1);
        f = __half22float2(v6); a0 = fmaf(__int_as_float(q3.y), f.x, a0); a1 = fmaf(__int_as_float(q3.y), f.y, a1);
        f = __half22float2(v7); a0 = fmaf(__int_as_float(q3.w), f.x, a0); a1 = fmaf(__int_as_float(q3.w), f.y, a1);
    }
#pragma unroll 1
    for (; i + 2 <= end; i += 2) {
        int4 q = __ldg((const int4*)(g_csr + i));
        __half2 va = __ldg((const __half2*)(hin + q.x * HD) + lane);
        __half2 vb = __ldg((const __half2*)(hin + q.z * HD) + lane);
        float2 fa = __half22float2(va), fb = __half22float2(vb);
        a0 = fmaf(__int_as_float(q.y), fa.x, a0); a1 = fmaf(__int_as_float(q.y), fa.y, a1);
        a0 = fmaf(__int_as_float(q.w), fb.x, a0); a1 = fmaf(__int_as_float(q.w), fb.y, a1);
    }
    if (i < end) {
        int2 p = __ldg(g_csr + i);
        __half2 v = __ldg((const __half2*)(hin + p.x * HD) + lane);
        float2 f = __half22float2(v);
        float w = __int_as_float(p.y);
        a0 = fmaf(w, f.x, a0); a1 = fmaf(w, f.y, a1);
    }
    ((__half2*)(g_agg + node * HD))[lane] = __floats2half2_rn(a0, a1);
}

// ---------------- tensor-core node GEMM: out = [agg|h] @ [Wrel;Wroot] + b -----------
template <int LAYER>
__global__ void __launch_bounds__(256) gemm_mma_kernel(
        const float* __restrict__ bias, const int* __restrict__ batch, int n) {
    __shared__ __align__(16) __half sA[128 * 128];   // [node][k], swizzled
    __shared__ __align__(16) __half sWt[64 * 128];   // [j][k],    swizzled
    const __half* Hin = (LAYER == 2) ? g_h1 : g_h2;
    const __half* Wt = g_w16 + ((LAYER == 2) ? 0 : 8192);
    int tid = threadIdx.x;
    int n0 = blockIdx.x * 128;

#pragma unroll
    for (int i = 0; i < 4; i++)
        ((int4*)sWt)[tid + i * 256] = __ldg((const int4*)Wt + tid + i * 256);

    for (int i = tid; i < 2048; i += 256) {
        int node = i >> 4, c4 = i & 15;
        int gn = n0 + node;
        int2 ra = make_int2(0, 0), rh = make_int2(0, 0);
        if (gn < n) {
            ra = __ldg((const int2*)(g_agg + gn * HD) + c4);
            rh = __ldg((const int2*)(Hin + gn * HD) + c4);
        }
        int k = c4 * 4;
        int chunk = (k >> 3) ^ (node & 7);
        __half* p = sA + node * 128 + chunk * 8 + (k & 7);
        *(int*)p       = ra.x;
        *(int*)(p + 2) = ra.y;
        k = 64 + c4 * 4;
        chunk = (k >> 3) ^ (node & 7);
        p = sA + node * 128 + chunk * 8 + (k & 7);
        *(int*)p       = rh.x;
        *(int*)(p + 2) = rh.y;
    }
    __syncthreads();

    int lane = tid & 31, warp = tid >> 5;
    int wm = warp & 3, wn = warp >> 2;
    int m0 = wm * 32;
    int gid = lane >> 2, tid4 = lane & 3;

    float acc[2][4][4];
#pragma unroll
    for (int mt = 0; mt < 2; mt++)
#pragma unroll
        for (int nt = 0; nt < 4; nt++)
#pragma unroll
            for (int q = 0; q < 4; q++) acc[mt][nt][q] = 0.f;

#pragma unroll
    for (int ks = 0; ks < 8; ks++) {
        int k0 = ks * 16 + tid4 * 2;
        int k1 = k0 + 8;
        uint32_t a[2][4];
#pragma unroll
        for (int mt = 0; mt < 2; mt++) {
            int row0 = m0 + mt * 16 + gid;
            int row1 = row0 + 8;
            a[mt][0] = ld_sw(sA, row0, k0);
            a[mt][1] = ld_sw(sA, row1, k0);
            a[mt][2] = ld_sw(sA, row0, k1);
            a[mt][3] = ld_sw(sA, row1, k1);
        }
#pragma unroll
        for (int nt = 0; nt < 4; nt++) {
            int j = wn * 32 + nt * 8 + gid;
            uint32_t b0 = ld_sw(sWt, j, k0);
            uint32_t b1 = ld_sw(sWt, j, k1);
            mma16816(acc[0][nt], a[0][0], a[0][1], a[0][2], a[0][3], b0, b1);
            mma16816(acc[1][nt], a[1][0], a[1][1], a[1][2], a[1][3], b0, b1);
        }
    }

    int crow = gid;
    int ccol = tid4 * 2;
#pragma unroll
    for (int nt = 0; nt < 4; nt++) {
        int j = wn * 32 + nt * 8 + ccol;
        float2 bb = __ldg((const float2*)(bias + j));
#pragma unroll
        for (int mt = 0; mt < 2; mt++) {
            int nodeA = n0 + m0 + mt * 16 + crow;
            int nodeB = nodeA + 8;
            float o0 = acc[mt][nt][0] + bb.x;
            float o1 = acc[mt][nt][1] + bb.y;
            float o2 = acc[mt][nt][2] + bb.x;
            float o3 = acc[mt][nt][3] + bb.y;
            if (LAYER == 2) {
                o0 = fmaxf(o0, 0.f); o1 = fmaxf(o1, 0.f);
                o2 = fmaxf(o2, 0.f); o3 = fmaxf(o3, 0.f);
                if (nodeA < n) *(__half2*)(g_h2 + nodeA * HD + j) = __floats2half2_rn(o0, o1);
                if (nodeB < n) *(__half2*)(g_h2 + nodeB * HD + j) = __floats2half2_rn(o2, o3);
            } else {
                if (nodeA < n) red_add_v2(g_sums + __ldg(batch + nodeA) * HD + j, o0, o1);
                if (nodeB < n) red_add_v2(g_sums + __ldg(batch + nodeB) * HD + j, o2, o3);
            }
        }
    }
}

// ---------------- head ----------------
__global__ void head_kernel(const float* __restrict__ Wlin, const float* __restrict__ blin,
                            float* __restrict__ out, int g) {
    int idx = blockIdx.x * blockDim.x + threadIdx.x;
    if (idx >= g * 2) return;
    int gi = idx >> 1, c = idx & 1;
    float inv = 1.0f / fmaxf(g_cnt[gi], 1.0f);
    float acc = 0.f;
#pragma unroll
    for (int k = 0; k < HD; k++)
        acc = fmaf(g_sums[gi * HD + k], Wlin[k * 2 + c], acc);
    out[idx] = fmaf(acc, inv, blin[c]);
}

extern "C" void kernel_launch(void* const* d_in, const int* in_sizes, int n_in,
                              void* d_out, int out_size) {
    const float* x      = (const float*)d_in[0];
    const int*   ei     = (const int*)d_in[1];
    const int*   batch  = (const int*)d_in[2];
    const float* ew     = (const float*)d_in[3];
    const float* W1rel  = (const float*)d_in[4];
    const float* b1     = (const float*)d_in[5];
    const float* W1root = (const float*)d_in[6];
    const float* W2rel  = (const float*)d_in[7];
    const float* b2     = (const float*)d_in[8];
    const float* W2root = (const float*)d_in[9];
    const float* W3rel  = (const float*)d_in[10];
    const float* b3     = (const float*)d_in[11];
    const float* W3root = (const float*)d_in[12];
    const float* Wlin   = (const float*)d_in[13];
    const float* blin   = (const float*)d_in[14];

    int N = in_sizes[0];        // x is [N,1]
    int E = in_sizes[3];        // edge_weight is [E]
    int G = out_size / 2;

    const int* src = ei;
    const int* dst = ei + E;
    float* out = (float*)d_out;

    init_kernel<<<256, 256>>>(W2rel, W2root, W3rel, W3root, N, G);
    hist_kernel<<<(E / 8 + 256) / 256, 256>>>(dst, E);
    offs_kernel<<<(N + 255) / 256, 256>>>(N);
    fill_kernel<<<(E / 2 + 256) / 256, 256>>>(src, dst, ew, x, E);

    node1_kernel<<<(N * 8 + 255) / 256, 256>>>(x, batch, W1rel, b1, W1root, N);
    aggH_kernel<2><<<(N * 32 + 255) / 256, 256>>>(N);
    gemm_mma_kernel<2><<<(N + 127) / 128, 256>>>(b2, batch, N);
    aggH_kernel<3><<<(N * 32 + 255) / 256, 256>>>(N);
    gemm_mma_kernel<3><<<(N + 127) / 128, 256>>>(b3, batch, N);
    head_kernel<<<(G * 2 + 255) / 256, 256>>>(Wlin, blin, out, G);
}

// round 16
// speedup vs baseline: 1.1077x; 1.0546x over previous
#include <cuda_runtime.h>
#include <cuda_fp16.h>
#include <cstdint>

#define HD 64
#define FULL 0xFFFFFFFFu

static const int N_CAP = 100000;
static const int E_CAP = 1200000;
static const int G_CAP = 256;

// Scratch (allocation-free: __device__ globals; only referenced in device code)
__device__ int    g_deg[N_CAP];
__device__ int    g_off[N_CAP];
__device__ int    g_rank[E_CAP];              // edge's rank within its dst segment
__device__ int    g_total;
__device__ __align__(16) int2 g_csr[E_CAP];   // {src, w bits}
__device__ float  g_agg1[N_CAP];
__device__ __half g_h1[N_CAP * HD];
__device__ __half g_h2[N_CAP * HD];
__device__ __half g_agg[N_CAP * HD];
__device__ __align__(16) __half g_w16[2 * 64 * 128];  // pre-swizzled [Wrel;Wroot]^T fp16
__device__ float  g_sums[G_CAP * HD];
__device__ float  g_cnt[G_CAP];

__device__ __forceinline__ void red_add_v2(float* p, float x, float y) {
    asm volatile("red.global.add.v2.f32 [%0], {%1,%2};"
                 :: "l"(p), "f"(x), "f"(y) : "memory");
}
__device__ __forceinline__ void red_add_f(float* p, float x) {
    asm volatile("red.global.add.f32 [%0], %1;" :: "l"(p), "f"(x) : "memory");
}

// mma.sync m16n8k16 fp16 -> fp32
__device__ __forceinline__ void mma16816(float* c,
        uint32_t a0, uint32_t a1, uint32_t a2, uint32_t a3,
        uint32_t b0, uint32_t b1) {
    asm volatile(
        "mma.sync.aligned.m16n8k16.row.col.f32.f16.f16.f32 "
        "{%0,%1,%2,%3}, {%4,%5,%6,%7}, {%8,%9}, {%0,%1,%2,%3};"
        : "+f"(c[0]), "+f"(c[1]), "+f"(c[2]), "+f"(c[3])
        : "r"(a0), "r"(a1), "r"(a2), "r"(a3), "r"(b0), "r"(b1));
}

// swizzled half2 load from a [row][128] fp16 tile: 16B chunk c stored at c^(row&7)
__device__ __forceinline__ uint32_t ld_sw(const __half* base, int row, int k) {
    int chunk = (k >> 3) ^ (row & 7);
    return *(const uint32_t*)(base + row * 128 + chunk * 8 + (k & 7));
}

// ---------------- init + weight preconversion ----------------
__global__ void init_kernel(const float* __restrict__ W2rel, const float* __restrict__ W2root,
                            const float* __restrict__ W3rel, const float* __restrict__ W3root,
                            int n, int g) {
    int i = blockIdx.x * blockDim.x + threadIdx.x;
    int stride = gridDim.x * blockDim.x;
    for (int k = i; k < n; k += stride) { g_deg[k] = 0; g_agg1[k] = 0.f; }
    int sv = g * HD;
    for (int k = i; k < sv; k += stride) g_sums[k] = 0.f;
    for (int k = i; k < g; k += stride) g_cnt[k] = 0.f;
    if (i == 0) g_total = 0;
    for (int idx = i; idx < 16384; idx += stride) {
        int L = idx >> 13;
        int r = idx & 8191;
        int k = r >> 6, j = r & 63;
        const float* Wrel  = L ? W3rel : W2rel;
        const float* Wroot = L ? W3root : W2root;
        float wv = (k < 64) ? __ldg(Wrel + k * 64 + j) : __ldg(Wroot + (k - 64) * 64 + j);
        int chunk = (k >> 3) ^ (j & 7);
        g_w16[L * 8192 + j * 128 + chunk * 8 + (k & 7)] = __float2half_rn(wv);
    }
}

// ---------------- CSR build: hist also records each edge's segment rank ----------------
__global__ void hist_kernel(const int* __restrict__ dst, int E) {
    int i = (blockIdx.x * blockDim.x + threadIdx.x) * 8;
    if (i + 7 < E) {
        int4 d0 = __ldg((const int4*)(dst + i));
        int4 d1 = __ldg((const int4*)(dst + i + 4));
        int4 r0, r1;
        r0.x = atomicAdd(&g_deg[d0.x], 1);
        r0.y = atomicAdd(&g_deg[d0.y], 1);
        r0.z = atomicAdd(&g_deg[d0.z], 1);
        r0.w = atomicAdd(&g_deg[d0.w], 1);
        r1.x = atomicAdd(&g_deg[d1.x], 1);
        r1.y = atomicAdd(&g_deg[d1.y], 1);
        r1.z = atomicAdd(&g_deg[d1.z], 1);
        r1.w = atomicAdd(&g_deg[d1.w], 1);
        *(int4*)(g_rank + i)     = r0;
        *(int4*)(g_rank + i + 4) = r1;
    } else {
        for (int e = i; e < E; e++) g_rank[e] = atomicAdd(&g_deg[dst[e]], 1);
    }
}

// warp-aggregated: inclusive scan, one atomicAdd per warp
__global__ void offs_kernel(int n) {
    int i = blockIdx.x * blockDim.x + threadIdx.x;
    int lane = threadIdx.x & 31;
    int d = (i < n) ? g_deg[i] : 0;
    int s = d;
#pragma unroll
    for (int o = 1; o < 32; o <<= 1) {
        int t = __shfl_up_sync(FULL, s, o);
        if (lane >= o) s += t;
    }
    int wsum = __shfl_sync(FULL, s, 31);
    int base = 0;
    if (lane == 31) base = atomicAdd(&g_total, wsum);
    base = __shfl_sync(FULL, base, 31);
    if (i < n) g_off[i] = base + s - d;    // exclusive
}

// fill CSR (atomic-free slots) + layer-1 scalar aggregation (agg1[dst] += w * x[src])
__global__ void fill_kernel(const int* __restrict__ src, const int* __restrict__ dst,
                            const float* __restrict__ ew, const float* __restrict__ x, int E) {
    int i = (blockIdx.x * blockDim.x + threadIdx.x) * 4;
    if (i + 3 < E) {
        int4 d = __ldg((const int4*)(dst + i));
        int4 s = __ldg((const int4*)(src + i));
        float4 w = __ldg((const float4*)(ew + i));
        int4 r = *(const int4*)(g_rank + i);
        int p0 = __ldg(g_off + d.x) + r.x;
        int p1 = __ldg(g_off + d.y) + r.y;
        int p2 = __ldg(g_off + d.z) + r.z;
        int p3 = __ldg(g_off + d.w) + r.w;
        float x0 = __ldg(x + s.x), x1 = __ldg(x + s.y);
        float x2 = __ldg(x + s.z), x3 = __ldg(x + s.w);
        g_csr[p0] = make_int2(s.x, __float_as_int(w.x));
        g_csr[p1] = make_int2(s.y, __float_as_int(w.y));
        g_csr[p2] = make_int2(s.z, __float_as_int(w.z));
        g_csr[p3] = make_int2(s.w, __float_as_int(w.w));
        red_add_f(&g_agg1[d.x], w.x * x0);
        red_add_f(&g_agg1[d.y], w.y * x1);
        red_add_f(&g_agg1[d.z], w.z * x2);
        red_add_f(&g_agg1[d.w], w.w * x3);
    } else {
        for (int e = i; e < E; e++) {
            int d = __ldg(dst + e), s = __ldg(src + e);
            float w = __ldg(ew + e);
            int p = __ldg(g_off + d) + g_rank[e];
            g_csr[p] = make_int2(s, __float_as_int(w));
            red_add_f(&g_agg1[d], w * __ldg(x + s));
        }
    }
}

// ---------------- layer 1 node transform (agg1 precomputed by fill) ----------------
__global__ void node1_kernel(const float* __restrict__ x, const int* __restrict__ batch,
                             const float* __restrict__ Wrel, const float* __restrict__ b,
                             const float* __restrict__ Wroot, int n) {
    int idx = blockIdx.x * blockDim.x + threadIdx.x;
    if (idx >= n * 8) return;
    int node = idx >> 3, c8 = idx & 7;
    float a = g_agg1[node];
    float xv = __ldg(x + node);
    float4 wr0 = __ldg((const float4*)Wrel + c8 * 2);
    float4 wr1 = __ldg((const float4*)Wrel + c8 * 2 + 1);
    float4 wo0 = __ldg((const float4*)Wroot + c8 * 2);
    float4 wo1 = __ldg((const float4*)Wroot + c8 * 2 + 1);
    float4 bb0 = __ldg((const float4*)b + c8 * 2);
    float4 bb1 = __ldg((const float4*)b + c8 * 2 + 1);
    float h0 = fmaxf(fmaf(a, wr0.x, fmaf(xv, wo0.x, bb0.x)), 0.f);
    float h1 = fmaxf(fmaf(a, wr0.y, fmaf(xv, wo0.y, bb0.y)), 0.f);
    float h2 = fmaxf(fmaf(a, wr0.z, fmaf(xv, wo0.z, bb0.z)), 0.f);
    float h3 = fmaxf(fmaf(a, wr0.w, fmaf(xv, wo0.w, bb0.w)), 0.f);
    float h4 = fmaxf(fmaf(a, wr1.x, fmaf(xv, wo1.x, bb1.x)), 0.f);
    float h5 = fmaxf(fmaf(a, wr1.y, fmaf(xv, wo1.y, bb1.y)), 0.f);
    float h6 = fmaxf(fmaf(a, wr1.z, fmaf(xv, wo1.z, bb1.z)), 0.f);
    float h7 = fmaxf(fmaf(a, wr1.w, fmaf(xv, wo1.w, bb1.w)), 0.f);
    __half2 p0 = __floats2half2_rn(h0, h1);
    __half2 p1 = __floats2half2_rn(h2, h3);
    __half2 p2 = __floats2half2_rn(h4, h5);
    __half2 p3 = __floats2half2_rn(h6, h7);
    *(int4*)(g_h1 + node * HD + c8 * 8) =
        make_int4(*(int*)&p0, *(int*)&p1, *(int*)&p2, *(int*)&p3);
    if (c8 == 0) atomicAdd(&g_cnt[batch[node]], 1.0f);
}

// ---------------- H-layer aggregation: warp-per-node, lane = channel pair ----------
template <int LAYER>
__global__ void aggH_kernel(int n) {
    const __half* __restrict__ hin = (LAYER == 2) ? g_h1 : g_h2;
    int gtid = blockIdx.x * blockDim.x + threadIdx.x;
    int node = gtid >> 5, lane = gtid & 31;
    if (node >= n) return;

    int off = g_off[node], end = off + (g_off[node + 1 <= n - 1 ? node + 1 : node] - g_off[node]);
    // NOTE: deg must come from g_deg (offsets are not sorted-contiguous); use g_deg.
    end = off + g_deg[node];
    float a0 = 0.f, a1 = 0.f;

    int i = off;
#pragma unroll 1
    for (; i + 8 <= end; i += 8) {
        int2 p[8];
#pragma unroll
        for (int j = 0; j < 8; j++) p[j] = __ldg(g_csr + i + j);
        __half2 v[8];
#pragma unroll
        for (int j = 0; j < 8; j++)
            v[j] = __ldg((const __half2*)(hin + p[j].x * HD) + lane);
#pragma unroll
        for (int j = 0; j < 8; j++) {
            float2 f = __half22float2(v[j]);
            float w = __int_as_float(p[j].y);
            a0 = fmaf(w, f.x, a0); a1 = fmaf(w, f.y, a1);
        }
    }
#pragma unroll 1
    for (; i + 4 <= end; i += 4) {
        int2 p[4];
#pragma unroll
        for (int j = 0; j < 4; j++) p[j] = __ldg(g_csr + i + j);
        __half2 v[4];
#pragma unroll
        for (int j = 0; j < 4; j++)
            v[j] = __ldg((const __half2*)(hin + p[j].x * HD) + lane);
#pragma unroll
        for (int j = 0; j < 4; j++) {
            float2 f = __half22float2(v[j]);
            float w = __int_as_float(p[j].y);
            a0 = fmaf(w, f.x, a0); a1 = fmaf(w, f.y, a1);
        }
    }
    for (; i < end; i++) {
        int2 p = __ldg(g_csr + i);
        __half2 v = __ldg((const __half2*)(hin + p.x * HD) + lane);
        float2 f = __half22float2(v);
        float w = __int_as_float(p.y);
        a0 = fmaf(w, f.x, a0); a1 = fmaf(w, f.y, a1);
    }
    ((__half2*)(g_agg + node * HD))[lane] = __floats2half2_rn(a0, a1);
}

// ---------------- tensor-core node GEMM: out = [agg|h] @ [Wrel;Wroot] + b -----------
template <int LAYER>
__global__ void __launch_bounds__(256) gemm_mma_kernel(
        const float* __restrict__ bias, const int* __restrict__ batch, int n) {
    __shared__ __align__(16) __half sA[128 * 128];   // [node][k], swizzled
    __shared__ __align__(16) __half sWt[64 * 128];   // [j][k],    swizzled
    const __half* Hin = (LAYER == 2) ? g_h1 : g_h2;
    const __half* Wt = g_w16 + ((LAYER == 2) ? 0 : 8192);
    int tid = threadIdx.x;
    int n0 = blockIdx.x * 128;

#pragma unroll
    for (int i = 0; i < 4; i++)
        ((int4*)sWt)[tid + i * 256] = __ldg((const int4*)Wt + tid + i * 256);

    for (int i = tid; i < 2048; i += 256) {
        int node = i >> 4, c4 = i & 15;
        int gn = n0 + node;
        int2 ra = make_int2(0, 0), rh = make_int2(0, 0);
        if (gn < n) {
            ra = __ldg((const int2*)(g_agg + gn * HD) + c4);
            rh = __ldg((const int2*)(Hin + gn * HD) + c4);
        }
        int k = c4 * 4;
        int chunk = (k >> 3) ^ (node & 7);
        __half* p = sA + node * 128 + chunk * 8 + (k & 7);
        *(int*)p       = ra.x;
        *(int*)(p + 2) = ra.y;
        k = 64 + c4 * 4;
        chunk = (k >> 3) ^ (node & 7);
        p = sA + node * 128 + chunk * 8 + (k & 7);
        *(int*)p       = rh.x;
        *(int*)(p + 2) = rh.y;
    }
    __syncthreads();

    int lane = tid & 31, warp = tid >> 5;
    int wm = warp & 3, wn = warp >> 2;
    int m0 = wm * 32;
    int gid = lane >> 2, tid4 = lane & 3;

    float acc[2][4][4];
#pragma unroll
    for (int mt = 0; mt < 2; mt++)
#pragma unroll
        for (int nt = 0; nt < 4; nt++)
#pragma unroll
            for (int q = 0; q < 4; q++) acc[mt][nt][q] = 0.f;

#pragma unroll
    for (int ks = 0; ks < 8; ks++) {
        int k0 = ks * 16 + tid4 * 2;
        int k1 = k0 + 8;
        uint32_t a[2][4];
#pragma unroll
        for (int mt = 0; mt < 2; mt++) {
            int row0 = m0 + mt * 16 + gid;
            int row1 = row0 + 8;
            a[mt][0] = ld_sw(sA, row0, k0);
            a[mt][1] = ld_sw(sA, row1, k0);
            a[mt][2] = ld_sw(sA, row0, k1);
            a[mt][3] = ld_sw(sA, row1, k1);
        }
#pragma unroll
        for (int nt = 0; nt < 4; nt++) {
            int j = wn * 32 + nt * 8 + gid;
            uint32_t b0 = ld_sw(sWt, j, k0);
            uint32_t b1 = ld_sw(sWt, j, k1);
            mma16816(acc[0][nt], a[0][0], a[0][1], a[0][2], a[0][3], b0, b1);
            mma16816(acc[1][nt], a[1][0], a[1][1], a[1][2], a[1][3], b0, b1);
        }
    }

    int crow = gid;
    int ccol = tid4 * 2;
#pragma unroll
    for (int nt = 0; nt < 4; nt++) {
        int j = wn * 32 + nt * 8 + ccol;
        float2 bb = __ldg((const float2*)(bias + j));
#pragma unroll
        for (int mt = 0; mt < 2; mt++) {
            int nodeA = n0 + m0 + mt * 16 + crow;
            int nodeB = nodeA + 8;
            float o0 = acc[mt][nt][0] + bb.x;
            float o1 = acc[mt][nt][1] + bb.y;
            float o2 = acc[mt][nt][2] + bb.x;
            float o3 = acc[mt][nt][3] + bb.y;
            if (LAYER == 2) {
                o0 = fmaxf(o0, 0.f); o1 = fmaxf(o1, 0.f);
                o2 = fmaxf(o2, 0.f); o3 = fmaxf(o3, 0.f);
                if (nodeA < n) *(__half2*)(g_h2 + nodeA * HD + j) = __floats2half2_rn(o0, o1);
                if (nodeB < n) *(__half2*)(g_h2 + nodeB * HD + j) = __floats2half2_rn(o2, o3);
            } else {
                if (nodeA < n) red_add_v2(g_sums + __ldg(batch + nodeA) * HD + j, o0, o1);
                if (nodeB < n) red_add_v2(g_sums + __ldg(batch + nodeB) * HD + j, o2, o3);
            }
        }
    }
}

// ---------------- head ----------------
__global__ void head_kernel(const float* __restrict__ Wlin, const float* __restrict__ blin,
                            float* __restrict__ out, int g) {
    int idx = blockIdx.x * blockDim.x + threadIdx.x;
    if (idx >= g * 2) return;
    int gi = idx >> 1, c = idx & 1;
    float inv = 1.0f / fmaxf(g_cnt[gi], 1.0f);
    float acc = 0.f;
#pragma unroll
    for (int k = 0; k < HD; k++)
        acc = fmaf(g_sums[gi * HD + k], Wlin[k * 2 + c], acc);
    out[idx] = fmaf(acc, inv, blin[c]);
}

extern "C" void kernel_launch(void* const* d_in, const int* in_sizes, int n_in,
                              void* d_out, int out_size) {
    const float* x      = (const float*)d_in[0];
    const int*   ei     = (const int*)d_in[1];
    const int*   batch  = (const int*)d_in[2];
    const float* ew     = (const float*)d_in[3];
    const float* W1rel  = (const float*)d_in[4];
    const float* b1     = (const float*)d_in[5];
    const float* W1root = (const float*)d_in[6];
    const float* W2rel  = (const float*)d_in[7];
    const float* b2     = (const float*)d_in[8];
    const float* W2root = (const float*)d_in[9];
    const float* W3rel  = (const float*)d_in[10];
    const float* b3     = (const float*)d_in[11];
    const float* W3root = (const float*)d_in[12];
    const float* Wlin   = (const float*)d_in[13];
    const float* blin   = (const float*)d_in[14];

    int N = in_sizes[0];        // x is [N,1]
    int E = in_sizes[3];        // edge_weight is [E]
    int G = out_size / 2;

    const int* src = ei;
    const int* dst = ei + E;
    float* out = (float*)d_out;

    init_kernel<<<256, 256>>>(W2rel, W2root, W3rel, W3root, N, G);
    hist_kernel<<<(E / 8 + 256) / 256, 256>>>(dst, E);
    offs_kernel<<<(N + 255) / 256, 256>>>(N);
    fill_kernel<<<(E / 4 + 256) / 256, 256>>>(src, dst, ew, x, E);

    node1_kernel<<<(N * 8 + 255) / 256, 256>>>(x, batch, W1rel, b1, W1root, N);
    aggH_kernel<2><<<(N * 32 + 255) / 256, 256>>>(N);
    gemm_mma_kernel<2><<<(N + 127) / 128, 256>>>(b2, batch, N);
    aggH_kernel<3><<<(N * 32 + 255) / 256, 256>>>(N);
    gemm_mma_kernel<3><<<(N + 127) / 128, 256>>>(b3, batch, N);
    head_kernel<<<(G * 2 + 255) / 256, 256>>>(Wlin, blin, out, G);
}

// round 17
// speedup vs baseline: 1.1301x; 1.0202x over previous
#include <cuda_runtime.h>
#include <cuda_fp16.h>
#include <cstdint>

#define HD 64
#define FULL 0xFFFFFFFFu

#define PDL_TRIGGER() asm volatile("griddepcontrol.launch_dependents;" ::: "memory")
#define PDL_WAIT()    asm volatile("griddepcontrol.wait;" ::: "memory")

static const int N_CAP = 100000;
static const int E_CAP = 1200000;
static const int G_CAP = 256;

// Scratch (allocation-free: __device__ globals; only referenced in device code)
__device__ int    g_deg[N_CAP];
__device__ int    g_off[N_CAP];
__device__ int    g_rank[E_CAP];              // edge's rank within its dst segment
__device__ int    g_total;
__device__ __align__(16) int2 g_csr[E_CAP];   // {src, w bits}
__device__ float  g_agg1[N_CAP];
__device__ __half g_h1[N_CAP * HD];
__device__ __half g_h2[N_CAP * HD];
__device__ __half g_agg[N_CAP * HD];
__device__ __align__(16) __half g_w16[2 * 64 * 128];  // pre-swizzled [Wrel;Wroot]^T fp16
__device__ float  g_sums[G_CAP * HD];
__device__ float  g_cnt[G_CAP];

__device__ __forceinline__ void red_add_v2(float* p, float x, float y) {
    asm volatile("red.global.add.v2.f32 [%0], {%1,%2};"
                 :: "l"(p), "f"(x), "f"(y) : "memory");
}
__device__ __forceinline__ void red_add_f(float* p, float x) {
    asm volatile("red.global.add.f32 [%0], %1;" :: "l"(p), "f"(x) : "memory");
}

// mma.sync m16n8k16 fp16 -> fp32
__device__ __forceinline__ void mma16816(float* c,
        uint32_t a0, uint32_t a1, uint32_t a2, uint32_t a3,
        uint32_t b0, uint32_t b1) {
    asm volatile(
        "mma.sync.aligned.m16n8k16.row.col.f32.f16.f16.f32 "
        "{%0,%1,%2,%3}, {%4,%5,%6,%7}, {%8,%9}, {%0,%1,%2,%3};"
        : "+f"(c[0]), "+f"(c[1]), "+f"(c[2]), "+f"(c[3])
        : "r"(a0), "r"(a1), "r"(a2), "r"(a3), "r"(b0), "r"(b1));
}

// swizzled half2 load from a [row][128] fp16 tile: 16B chunk c stored at c^(row&7)
__device__ __forceinline__ uint32_t ld_sw(const __half* base, int row, int k) {
    int chunk = (k >> 3) ^ (row & 7);
    return *(const uint32_t*)(base + row * 128 + chunk * 8 + (k & 7));
}

// ---------------- init + weight preconversion ----------------
__global__ void init_kernel(const float* __restrict__ W2rel, const float* __restrict__ W2root,
                            const float* __restrict__ W3rel, const float* __restrict__ W3root,
                            int n, int g) {
    PDL_TRIGGER();
    int i = blockIdx.x * blockDim.x + threadIdx.x;
    int stride = gridDim.x * blockDim.x;
    for (int k = i; k < n; k += stride) { g_deg[k] = 0; g_agg1[k] = 0.f; }
    int sv = g * HD;
    for (int k = i; k < sv; k += stride) g_sums[k] = 0.f;
    for (int k = i; k < g; k += stride) g_cnt[k] = 0.f;
    if (i == 0) g_total = 0;
    for (int idx = i; idx < 16384; idx += stride) {
        int L = idx >> 13;
        int r = idx & 8191;
        int k = r >> 6, j = r & 63;
        const float* Wrel  = L ? W3rel : W2rel;
        const float* Wroot = L ? W3root : W2root;
        float wv = (k < 64) ? __ldg(Wrel + k * 64 + j) : __ldg(Wroot + (k - 64) * 64 + j);
        int chunk = (k >> 3) ^ (j & 7);
        g_w16[L * 8192 + j * 128 + chunk * 8 + (k & 7)] = __float2half_rn(wv);
    }
}

// ---------------- CSR build: hist also records each edge's segment rank ----------------
__global__ void hist_kernel(const int* __restrict__ dst, int E) {
    PDL_TRIGGER();
    int i = (blockIdx.x * blockDim.x + threadIdx.x) * 8;
    if (i + 7 < E) {
        // prologue: pure-input loads, overlap predecessor tail
        int4 d0 = __ldg((const int4*)(dst + i));
        int4 d1 = __ldg((const int4*)(dst + i + 4));
        PDL_WAIT();
        int4 r0, r1;
        r0.x = atomicAdd(&g_deg[d0.x], 1);
        r0.y = atomicAdd(&g_deg[d0.y], 1);
        r0.z = atomicAdd(&g_deg[d0.z], 1);
        r0.w = atomicAdd(&g_deg[d0.w], 1);
        r1.x = atomicAdd(&g_deg[d1.x], 1);
        r1.y = atomicAdd(&g_deg[d1.y], 1);
        r1.z = atomicAdd(&g_deg[d1.z], 1);
        r1.w = atomicAdd(&g_deg[d1.w], 1);
        *(int4*)(g_rank + i)     = r0;
        *(int4*)(g_rank + i + 4) = r1;
    } else {
        PDL_WAIT();
        for (int e = i; e < E; e++) g_rank[e] = atomicAdd(&g_deg[dst[e]], 1);
    }
}

// warp-aggregated: inclusive scan, one atomicAdd per warp
__global__ void offs_kernel(int n) {
    PDL_TRIGGER();
    PDL_WAIT();
    int i = blockIdx.x * blockDim.x + threadIdx.x;
    int lane = threadIdx.x & 31;
    int d = (i < n) ? g_deg[i] : 0;
    int s = d;
#pragma unroll
    for (int o = 1; o < 32; o <<= 1) {
        int t = __shfl_up_sync(FULL, s, o);
        if (lane >= o) s += t;
    }
    int wsum = __shfl_sync(FULL, s, 31);
    int base = 0;
    if (lane == 31) base = atomicAdd(&g_total, wsum);
    base = __shfl_sync(FULL, base, 31);
    if (i < n) g_off[i] = base + s - d;    // exclusive
}

// fill CSR (atomic-free slots) + layer-1 scalar aggregation (agg1[dst] += w * x[src])
__global__ void fill_kernel(const int* __restrict__ src, const int* __restrict__ dst,
                            const float* __restrict__ ew, const float* __restrict__ x, int E) {
    PDL_TRIGGER();
    int i = (blockIdx.x * blockDim.x + threadIdx.x) * 4;
    if (i + 3 < E) {
        // prologue: pure-input loads (src/dst/ew/x), overlap offs tail
        int4 d = __ldg((const int4*)(dst + i));
        int4 s = __ldg((const int4*)(src + i));
        float4 w = __ldg((const float4*)(ew + i));
        float x0 = __ldg(x + s.x), x1 = __ldg(x + s.y);
        float x2 = __ldg(x + s.z), x3 = __ldg(x + s.w);
        PDL_WAIT();
        int4 r = *(const int4*)(g_rank + i);
        int p0 = __ldg(g_off + d.x) + r.x;
        int p1 = __ldg(g_off + d.y) + r.y;
        int p2 = __ldg(g_off + d.z) + r.z;
        int p3 = __ldg(g_off + d.w) + r.w;
        g_csr[p0] = make_int2(s.x, __float_as_int(w.x));
        g_csr[p1] = make_int2(s.y, __float_as_int(w.y));
        g_csr[p2] = make_int2(s.z, __float_as_int(w.z));
        g_csr[p3] = make_int2(s.w, __float_as_int(w.w));
        red_add_f(&g_agg1[d.x], w.x * x0);
        red_add_f(&g_agg1[d.y], w.y * x1);
        red_add_f(&g_agg1[d.z], w.z * x2);
        red_add_f(&g_agg1[d.w], w.w * x3);
    } else {
        PDL_WAIT();
        for (int e = i; e < E; e++) {
            int d = __ldg(dst + e), s = __ldg(src + e);
            float w = __ldg(ew + e);
            int p = __ldg(g_off + d) + g_rank[e];
            g_csr[p] = make_int2(s, __float_as_int(w));
            red_add_f(&g_agg1[d], w * __ldg(x + s));
        }
    }
}

// ---------------- layer 1 node transform (agg1 precomputed by fill) ----------------
__global__ void node1_kernel(const float* __restrict__ x, const int* __restrict__ batch,
                             const float* __restrict__ Wrel, const float* __restrict__ b,
                             const float* __restrict__ Wroot, int n) {
    PDL_TRIGGER();
    int idx = blockIdx.x * blockDim.x + threadIdx.x;
    if (idx >= n * 8) { PDL_WAIT(); return; }
    int node = idx >> 3, c8 = idx & 7;
    // prologue: pure-input loads
    float xv = __ldg(x + node);
    float4 wr0 = __ldg((const float4*)Wrel + c8 * 2);
    float4 wr1 = __ldg((const float4*)Wrel + c8 * 2 + 1);
    float4 wo0 = __ldg((const float4*)Wroot + c8 * 2);
    float4 wo1 = __ldg((const float4*)Wroot + c8 * 2 + 1);
    float4 bb0 = __ldg((const float4*)b + c8 * 2);
    float4 bb1 = __ldg((const float4*)b + c8 * 2 + 1);
    int bi = batch[node];
    PDL_WAIT();
    float a = g_agg1[node];
    float h0 = fmaxf(fmaf(a, wr0.x, fmaf(xv, wo0.x, bb0.x)), 0.f);
    float h1 = fmaxf(fmaf(a, wr0.y, fmaf(xv, wo0.y, bb0.y)), 0.f);
    float h2 = fmaxf(fmaf(a, wr0.z, fmaf(xv, wo0.z, bb0.z)), 0.f);
    float h3 = fmaxf(fmaf(a, wr0.w, fmaf(xv, wo0.w, bb0.w)), 0.f);
    float h4 = fmaxf(fmaf(a, wr1.x, fmaf(xv, wo1.x, bb1.x)), 0.f);
    float h5 = fmaxf(fmaf(a, wr1.y, fmaf(xv, wo1.y, bb1.y)), 0.f);
    float h6 = fmaxf(fmaf(a, wr1.z, fmaf(xv, wo1.z, bb1.z)), 0.f);
    float h7 = fmaxf(fmaf(a, wr1.w, fmaf(xv, wo1.w, bb1.w)), 0.f);
    __half2 p0 = __floats2half2_rn(h0, h1);
    __half2 p1 = __floats2half2_rn(h2, h3);
    __half2 p2 = __floats2half2_rn(h4, h5);
    __half2 p3 = __floats2half2_rn(h6, h7);
    *(int4*)(g_h1 + node * HD + c8 * 8) =
        make_int4(*(int*)&p0, *(int*)&p1, *(int*)&p2, *(int*)&p3);
    if (c8 == 0) atomicAdd(&g_cnt[bi], 1.0f);
}

// ---------------- H-layer aggregation: warp-per-node, lane = channel pair ----------
template <int LAYER>
__global__ void aggH_kernel(int n) {
    PDL_TRIGGER();
    PDL_WAIT();
    const __half* __restrict__ hin = (LAYER == 2) ? g_h1 : g_h2;
    int gtid = blockIdx.x * blockDim.x + threadIdx.x;
    int node = gtid >> 5, lane = gtid & 31;
    if (node >= n) return;

    int off = g_off[node], end = off + g_deg[node];
    float a0 = 0.f, a1 = 0.f;

    int i = off;
#pragma unroll 1
    for (; i + 8 <= end; i += 8) {
        int2 p[8];
#pragma unroll
        for (int j = 0; j < 8; j++) p[j] = __ldg(g_csr + i + j);
        __half2 v[8];
#pragma unroll
        for (int j = 0; j < 8; j++)
            v[j] = __ldg((const __half2*)(hin + p[j].x * HD) + lane);
#pragma unroll
        for (int j = 0; j < 8; j++) {
            float2 f = __half22float2(v[j]);
            float w = __int_as_float(p[j].y);
            a0 = fmaf(w, f.x, a0); a1 = fmaf(w, f.y, a1);
        }
    }
#pragma unroll 1
    for (; i + 4 <= end; i += 4) {
        int2 p[4];
#pragma unroll
        for (int j = 0; j < 4; j++) p[j] = __ldg(g_csr + i + j);
        __half2 v[4];
#pragma unroll
        for (int j = 0; j < 4; j++)
            v[j] = __ldg((const __half2*)(hin + p[j].x * HD) + lane);
#pragma unroll
        for (int j = 0; j < 4; j++) {
            float2 f = __half22float2(v[j]);
            float w = __int_as_float(p[j].y);
            a0 = fmaf(w, f.x, a0); a1 = fmaf(w, f.y, a1);
        }
    }
    for (; i < end; i++) {
        int2 p = __ldg(g_csr + i);
        __half2 v = __ldg((const __half2*)(hin + p.x * HD) + lane);
        float2 f = __half22float2(v);
        float w = __int_as_float(p.y);
        a0 = fmaf(w, f.x, a0); a1 = fmaf(w, f.y, a1);
    }
    ((__half2*)(g_agg + node * HD))[lane] = __floats2half2_rn(a0, a1);
}

// ---------------- tensor-core node GEMM: out = [agg|h] @ [Wrel;Wroot] + b -----------
template <int LAYER>
__global__ void __launch_bounds__(256) gemm_mma_kernel(
        const float* __restrict__ bias, const int* __restrict__ batch, int n) {
    PDL_TRIGGER();
    PDL_WAIT();
    __shared__ __align__(16) __half sA[128 * 128];   // [node][k], swizzled
    __shared__ __align__(16) __half sWt[64 * 128];   // [j][k],    swizzled
    const __half* Hin = (LAYER == 2) ? g_h1 : g_h2;
    const __half* Wt = g_w16 + ((LAYER == 2) ? 0 : 8192);
    int tid = threadIdx.x;
    int n0 = blockIdx.x * 128;

#pragma unroll
    for (int i = 0; i < 4; i++)
        ((int4*)sWt)[tid + i * 256] = __ldg((const int4*)Wt + tid + i * 256);

    for (int i = tid; i < 2048; i += 256) {
        int node = i >> 4, c4 = i & 15;
        int gn = n0 + node;
        int2 ra = make_int2(0, 0), rh = make_int2(0, 0);
        if (gn < n) {
            ra = __ldg((const int2*)(g_agg + gn * HD) + c4);
            rh = __ldg((const int2*)(Hin + gn * HD) + c4);
        }
        int k = c4 * 4;
        int chunk = (k >> 3) ^ (node & 7);
        __half* p = sA + node * 128 + chunk * 8 + (k & 7);
        *(int*)p       = ra.x;
        *(int*)(p + 2) = ra.y;
        k = 64 + c4 * 4;
        chunk = (k >> 3) ^ (node & 7);
        p = sA + node * 128 + chunk * 8 + (k & 7);
        *(int*)p       = rh.x;
        *(int*)(p + 2) = rh.y;
    }
    __syncthreads();

    int lane = tid & 31, warp = tid >> 5;
    int wm = warp & 3, wn = warp >> 2;
    int m0 = wm * 32;
    int gid = lane >> 2, tid4 = lane & 3;

    float acc[2][4][4];
#pragma unroll
    for (int mt = 0; mt < 2; mt++)
#pragma unroll
        for (int nt = 0; nt < 4; nt++)
#pragma unroll
            for (int q = 0; q < 4; q++) acc[mt][nt][q] = 0.f;

#pragma unroll
    for (int ks = 0; ks < 8; ks++) {
        int k0 = ks * 16 + tid4 * 2;
        int k1 = k0 + 8;
        uint32_t a[2][4];
#pragma unroll
        for (int mt = 0; mt < 2; mt++) {
            int row0 = m0 + mt * 16 + gid;
            int row1 = row0 + 8;
            a[mt][0] = ld_sw(sA, row0, k0);
            a[mt][1] = ld_sw(sA, row1, k0);
            a[mt][2] = ld_sw(sA, row0, k1);
            a[mt][3] = ld_sw(sA, row1, k1);
        }
#pragma unroll
        for (int nt = 0; nt < 4; nt++) {
            int j = wn * 32 + nt * 8 + gid;
            uint32_t b0 = ld_sw(sWt, j, k0);
            uint32_t b1 = ld_sw(sWt, j, k1);
            mma16816(acc[0][nt], a[0][0], a[0][1], a[0][2], a[0][3], b0, b1);
            mma16816(acc[1][nt], a[1][0], a[1][1], a[1][2], a[1][3], b0, b1);
        }
    }

    int crow = gid;
    int ccol = tid4 * 2;
#pragma unroll
    for (int nt = 0; nt < 4; nt++) {
        int j = wn * 32 + nt * 8 + ccol;
        float2 bb = __ldg((const float2*)(bias + j));
#pragma unroll
        for (int mt = 0; mt < 2; mt++) {
            int nodeA = n0 + m0 + mt * 16 + crow;
            int nodeB = nodeA + 8;
            float o0 = acc[mt][nt][0] + bb.x;
            float o1 = acc[mt][nt][1] + bb.y;
            float o2 = acc[mt][nt][2] + bb.x;
            float o3 = acc[mt][nt][3] + bb.y;
            if (LAYER == 2) {
                o0 = fmaxf(o0, 0.f); o1 = fmaxf(o1, 0.f);
                o2 = fmaxf(o2, 0.f); o3 = fmaxf(o3, 0.f);
                if (nodeA < n) *(__half2*)(g_h2 + nodeA * HD + j) = __floats2half2_rn(o0, o1);
                if (nodeB < n) *(__half2*)(g_h2 + nodeB * HD + j) = __floats2half2_rn(o2, o3);
            } else {
                if (nodeA < n) red_add_v2(g_sums + __ldg(batch + nodeA) * HD + j, o0, o1);
                if (nodeB < n) red_add_v2(g_sums + __ldg(batch + nodeB) * HD + j, o2, o3);
            }
        }
    }
}

// ---------------- head ----------------
__global__ void head_kernel(const float* __restrict__ Wlin, const float* __restrict__ blin,
                            float* __restrict__ out, int g) {
    PDL_WAIT();
    int idx = blockIdx.x * blockDim.x + threadIdx.x;
    if (idx >= g * 2) return;
    int gi = idx >> 1, c = idx & 1;
    float inv = 1.0f / fmaxf(g_cnt[gi], 1.0f);
    float acc = 0.f;
#pragma unroll
    for (int k = 0; k < HD; k++)
        acc = fmaf(g_sums[gi * HD + k], Wlin[k * 2 + c], acc);
    out[idx] = fmaf(acc, inv, blin[c]);
}

// PDL launch helper: PSS attribute so the kernel may launch during its predecessor
template <typename F, typename... Args>
static inline void launch_pdl(F kernel, int grid, int block, Args... args) {
    cudaLaunchConfig_t cfg = {};
    cfg.gridDim = dim3(grid, 1, 1);
    cfg.blockDim = dim3(block, 1, 1);
    cudaLaunchAttribute attr[1];
    attr[0].id = cudaLaunchAttributeProgrammaticStreamSerialization;
    attr[0].val.programmaticStreamSerializationAllowed = 1;
    cfg.attrs = attr;
    cfg.numAttrs = 1;
    cudaLaunchKernelEx(&cfg, kernel, args...);
}

extern "C" void kernel_launch(void* const* d_in, const int* in_sizes, int n_in,
                              void* d_out, int out_size) {
    const float* x      = (const float*)d_in[0];
    const int*   ei     = (const int*)d_in[1];
    const int*   batch  = (const int*)d_in[2];
    const float* ew     = (const float*)d_in[3];
    const float* W1rel  = (const float*)d_in[4];
    const float* b1     = (const float*)d_in[5];
    const float* W1root = (const float*)d_in[6];
    const float* W2rel  = (const float*)d_in[7];
    const float* b2     = (const float*)d_in[8];
    const float* W2root = (const float*)d_in[9];
    const float* W3rel  = (const float*)d_in[10];
    const float* b3     = (const float*)d_in[11];
    const float* W3root = (const float*)d_in[12];
    const float* Wlin   = (const float*)d_in[13];
    const float* blin   = (const float*)d_in[14];

    int N = in_sizes[0];        // x is [N,1]
    int E = in_sizes[3];        // edge_weight is [E]
    int G = out_size / 2;

    const int* src = ei;
    const int* dst = ei + E;
    float* out = (float*)d_out;

    init_kernel<<<256, 256>>>(W2rel, W2root, W3rel, W3root, N, G);
    launch_pdl(hist_kernel, (E / 8 + 256) / 256, 256, dst, E);
    launch_pdl(offs_kernel, (N + 255) / 256, 256, N);
    launch_pdl(fill_kernel, (E / 4 + 256) / 256, 256, src, dst, ew, x, E);
    launch_pdl(node1_kernel, (N * 8 + 255) / 256, 256, x, batch, W1rel, b1, W1root, N);
    launch_pdl(aggH_kernel<2>, (N * 32 + 255) / 256, 256, N);
    launch_pdl(gemm_mma_kernel<2>, (N + 127) / 128, 256, b2, batch, N);
    launch_pdl(aggH_kernel<3>, (N * 32 + 255) / 256, 256, N);
    launch_pdl(gemm_mma_kernel<3>, (N + 127) / 128, 256, b3, batch, N);
    launch_pdl(head_kernel, (G * 2 + 255) / 256, 256, Wlin, blin, out, G);
}